// round 3
// baseline (speedup 1.0000x reference)
#include <cuda_runtime.h>
#include <cuda_bf16.h>
#include <math.h>

#define N_NODES 25000
#define N_EDGES 400000
#define HID 64
#define EMB 8
#define N_GRAPHS 16
#define N_CLASSES 10
#define KDIM 512   /* EMB*HID */

// ---------------- scratch (device globals; no allocation allowed) ----------
__device__ float g_B[(size_t)N_NODES * KDIM];     // 51.2 MB  B[n, i*64+j]
__device__ float g_hA[N_NODES * HID];
__device__ float g_hB[N_NODES * HID];
__device__ float g_R[N_NODES * HID];              // relu(agg)
__device__ float g_D[(size_t)N_EDGES * EMB];      // directions in ORIGINAL edge order
__device__ int2  g_se[N_EDGES];                   // CSR-ordered {src, edge_id}
__device__ int   g_rowptr[N_NODES + 1];
__device__ int   g_cnt[N_NODES];
__device__ int   g_cur[N_NODES];
__device__ float g_sums[HID];
__device__ float g_sumsq[HID];
__device__ float g_pooled[N_GRAPHS * HID];
__device__ int   g_done;

// ---------------- f32x2 packed helpers ------------------------------------
__device__ __forceinline__ void ffma2(unsigned long long& d,
                                      unsigned long long a, unsigned long long b) {
    asm("fma.rn.f32x2 %0, %1, %2, %0;" : "+l"(d) : "l"(a), "l"(b));
}
__device__ __forceinline__ unsigned long long pack2(float x, float y) {
    unsigned long long r;
    asm("mov.b64 %0, {%1, %2};" : "=l"(r) : "f"(x), "f"(y));
    return r;
}
__device__ __forceinline__ float2 unpack2(unsigned long long v) {
    float2 r;
    asm("mov.b64 {%0, %1}, %2;" : "=f"(r.x), "=f"(r.y) : "l"(v));
    return r;
}

// ---------------- CSR build ------------------------------------------------
__global__ void k_zero_cc() {
    int i = blockIdx.x * blockDim.x + threadIdx.x;
    if (i < N_NODES) { g_cnt[i] = 0; g_cur[i] = 0; }
}

// histogram of dst + per-edge normalized direction (coalesced write, edge order)
__global__ void k_hist_dir(const int* __restrict__ src, const int* __restrict__ dst,
                           const float* __restrict__ c) {
    int e = blockIdx.x * blockDim.x + threadIdx.x;
    if (e >= N_EDGES) return;
    int s = src[e], t = dst[e];
    atomicAdd(&g_cnt[t], 1);
    float4 s0 = __ldg((const float4*)&c[s * EMB]);
    float4 s1 = __ldg((const float4*)&c[s * EMB + 4]);
    float4 t0 = __ldg((const float4*)&c[t * EMB]);
    float4 t1 = __ldg((const float4*)&c[t * EMB + 4]);
    float4 d0 = make_float4(s0.x - t0.x, s0.y - t0.y, s0.z - t0.z, s0.w - t0.w);
    float4 d1 = make_float4(s1.x - t1.x, s1.y - t1.y, s1.z - t1.z, s1.w - t1.w);
    float nn = d0.x * d0.x + d0.y * d0.y + d0.z * d0.z + d0.w * d0.w
             + d1.x * d1.x + d1.y * d1.y + d1.z * d1.z + d1.w * d1.w;
    float sc = 1.0f / fmaxf(sqrtf(nn), 1e-12f);
    d0.x *= sc; d0.y *= sc; d0.z *= sc; d0.w *= sc;
    d1.x *= sc; d1.y *= sc; d1.z *= sc; d1.w *= sc;
    *(float4*)&g_D[(size_t)e * EMB]     = d0;
    *(float4*)&g_D[(size_t)e * EMB + 4] = d1;
}

// single-block scan: 1024 threads x 25 contiguous counts each (25600 >= 25001)
__global__ void k_scan() {
    const int PER = 25;
    __shared__ int wsum[32];
    int tid = threadIdx.x, lane = tid & 31, wid = tid >> 5;
    int base = tid * PER;
    int v[PER];
    int s = 0;
    #pragma unroll
    for (int j = 0; j < PER; j++) {
        int i = base + j;
        int cv = (i < N_NODES) ? g_cnt[i] : 0;
        v[j] = s;
        s += cv;
    }
    int x = s;
    #pragma unroll
    for (int o = 1; o < 32; o <<= 1) {
        int t = __shfl_up_sync(0xffffffffu, x, o);
        if (lane >= o) x += t;
    }
    if (lane == 31) wsum[wid] = x;
    __syncthreads();
    if (wid == 0) {
        int w = wsum[lane];
        #pragma unroll
        for (int o = 1; o < 32; o <<= 1) {
            int t = __shfl_up_sync(0xffffffffu, w, o);
            if (lane >= o) w += t;
        }
        wsum[lane] = w;
    }
    __syncthreads();
    int off = x - s + (wid > 0 ? wsum[wid - 1] : 0);
    #pragma unroll
    for (int j = 0; j < PER; j++) {
        int i = base + j;
        if (i <= N_NODES) g_rowptr[i] = off + v[j];
    }
}

// scatter edge -> CSR slot; only 8 bytes scattered per edge
__global__ void k_scatter(const int* __restrict__ src, const int* __restrict__ dst) {
    int e = blockIdx.x * blockDim.x + threadIdx.x;
    if (e >= N_EDGES) return;
    int s = src[e], t = dst[e];
    int p = g_rowptr[t] + atomicAdd(&g_cur[t], 1);
    g_se[p] = make_int2(s, e);
}

// ---------------- edge aggregation: B[n,i,j] = sum_{e:dst=n} d_i * h[src,j] ----
__global__ void k_edge_agg(const float* __restrict__ feat, int hsel) {
    if (blockIdx.x == 0) {   // piggyback: zero per-layer reduction buffers
        int t = threadIdx.x;
        if (t < HID) { g_sums[t] = 0.f; g_sumsq[t] = 0.f; }
        if (t == 0) g_done = 0;
        for (int i = t; i < N_GRAPHS * HID; i += blockDim.x) g_pooled[i] = 0.f;
    }
    const float* __restrict__ h = (hsel == 0) ? feat : ((hsel == 1) ? g_hA : g_hB);
    int w = (blockIdx.x * blockDim.x + threadIdx.x) >> 5;
    int lane = threadIdx.x & 31;
    if (w >= N_NODES) return;
    int e0 = g_rowptr[w], e1 = g_rowptr[w + 1];
    float a0[EMB], a1[EMB];
    #pragma unroll
    for (int i = 0; i < EMB; i++) { a0[i] = 0.f; a1[i] = 0.f; }
    #pragma unroll 4
    for (int e = e0; e < e1; e++) {
        int2 se = __ldg(&g_se[e]);
        float4 d0 = __ldg((const float4*)&g_D[(size_t)se.y * EMB]);
        float4 d1 = __ldg((const float4*)&g_D[(size_t)se.y * EMB + 4]);
        float h0 = __ldg(&h[se.x * HID + lane]);
        float h1 = __ldg(&h[se.x * HID + 32 + lane]);
        a0[0] += d0.x * h0;  a1[0] += d0.x * h1;
        a0[1] += d0.y * h0;  a1[1] += d0.y * h1;
        a0[2] += d0.z * h0;  a1[2] += d0.z * h1;
        a0[3] += d0.w * h0;  a1[3] += d0.w * h1;
        a0[4] += d1.x * h0;  a1[4] += d1.x * h1;
        a0[5] += d1.y * h0;  a1[5] += d1.y * h1;
        a0[6] += d1.z * h0;  a1[6] += d1.z * h1;
        a0[7] += d1.w * h0;  a1[7] += d1.w * h1;
    }
    float* out = &g_B[(size_t)w * KDIM];
    #pragma unroll
    for (int i = 0; i < EMB; i++) {
        out[i * HID + lane] = a0[i];
        out[i * HID + 32 + lane] = a1[i];
    }
}

// ---------------- SGEMM: R = relu(B[25000,512] @ W[512,64]) + fused BN stats ---
// f32x2 packed-FMA microkernel: 4 rows x 8 cols per thread (cols as 4 packed pairs)
#define BM 128
#define BK 32
__global__ void k_gemm_relu(const float* __restrict__ W) {
    __shared__ float As[BM][BK + 4];   // stride 36 floats, 16B-aligned rows
    __shared__ float Bs[BK][HID];
    int tid = threadIdx.x;       // 256
    int tx = tid & 7;            // col group: cols tx*8 .. tx*8+7
    int ty = tid >> 3;           // row group: rows ty*4 .. ty*4+3
    int rowBase = blockIdx.x * BM;
    unsigned long long acc2[4][4];   // [row][colpair]
    #pragma unroll
    for (int r = 0; r < 4; r++)
        #pragma unroll
        for (int cc = 0; cc < 4; cc++) acc2[r][cc] = 0ull;

    for (int kb = 0; kb < KDIM; kb += BK) {
        #pragma unroll
        for (int it = 0; it < 4; it++) {
            int f = tid + 256 * it;
            int r = f >> 3;
            int q = f & 7;
            int grow = rowBase + r;
            float4 v = make_float4(0.f, 0.f, 0.f, 0.f);
            if (grow < N_NODES)
                v = *(const float4*)&g_B[(size_t)grow * KDIM + kb + q * 4];
            *(float4*)&As[r][q * 4] = v;
        }
        #pragma unroll
        for (int it = 0; it < 2; it++) {
            int f = tid + 256 * it;
            int k = f >> 4;
            int q = f & 15;
            *(float4*)&Bs[k][q * 4] = *(const float4*)&W[(kb + k) * HID + q * 4];
        }
        __syncthreads();
        #pragma unroll
        for (int kk = 0; kk < BK; kk++) {
            ulonglong2 b01 = *(const ulonglong2*)&Bs[kk][tx * 8];      // cols 0-3 (2 pairs)
            ulonglong2 b23 = *(const ulonglong2*)&Bs[kk][tx * 8 + 4];  // cols 4-7
            #pragma unroll
            for (int r = 0; r < 4; r++) {
                float a = As[ty * 4 + r][kk];
                unsigned long long a2 = pack2(a, a);
                ffma2(acc2[r][0], a2, b01.x);
                ffma2(acc2[r][1], a2, b01.y);
                ffma2(acc2[r][2], a2, b23.x);
                ffma2(acc2[r][3], a2, b23.y);
            }
        }
        __syncthreads();
    }
    // relu + store + per-thread column partials
    float colS[8], colS2[8];
    #pragma unroll
    for (int j = 0; j < 8; j++) { colS[j] = 0.f; colS2[j] = 0.f; }
    #pragma unroll
    for (int r = 0; r < 4; r++) {
        float v[8];
        #pragma unroll
        for (int cc = 0; cc < 4; cc++) {
            float2 p = unpack2(acc2[r][cc]);
            v[cc * 2]     = fmaxf(p.x, 0.f);
            v[cc * 2 + 1] = fmaxf(p.y, 0.f);
        }
        #pragma unroll
        for (int j = 0; j < 8; j++) { colS[j] += v[j]; colS2[j] += v[j] * v[j]; }
        int grow = rowBase + ty * 4 + r;
        if (grow < N_NODES) {
            *(float4*)&g_R[grow * HID + tx * 8]     = make_float4(v[0], v[1], v[2], v[3]);
            *(float4*)&g_R[grow * HID + tx * 8 + 4] = make_float4(v[4], v[5], v[6], v[7]);
        }
    }
    // reduce column partials: smem [32 row-groups][64 cols] for sum, then sumsq
    float* smr = &As[0][0];       // need 2048 floats x2; As has 4608
    __syncthreads();
    #pragma unroll
    for (int j = 0; j < 8; j++) {
        smr[ty * HID + tx * 8 + j] = colS[j];
        smr[2048 + ty * HID + tx * 8 + j] = colS2[j];
    }
    __syncthreads();
    if (tid < HID) {
        float s = 0.f, s2 = 0.f;
        #pragma unroll
        for (int g = 0; g < 32; g++) {
            s  += smr[g * HID + tid];
            s2 += smr[2048 + g * HID + tid];
        }
        atomicAdd(&g_sums[tid], s);
        atomicAdd(&g_sumsq[tid], s2);
    }
}

// ------- BN normalize + shortcut + pooling + (last block) classifier -------
__global__ void k_norm_pool(const float* __restrict__ feat, int hinsel, int houtsel,
                            const float* __restrict__ gamma, const float* __restrict__ beta,
                            const int* __restrict__ gids, int shortcut,
                            const float* __restrict__ cW1, const float* __restrict__ cb1,
                            const float* __restrict__ cg1, const float* __restrict__ cbt1,
                            const float* __restrict__ cW2, const float* __restrict__ cb2,
                            float* __restrict__ out, int accumulate) {
    const float* __restrict__ hin = (hinsel == 0) ? feat : ((hinsel == 1) ? g_hA : g_hB);
    float* hout = (houtsel == 1) ? g_hA : g_hB;
    int tid = threadIdx.x;        // 512 -> 8 nodes x 64 cols per block
    int k = tid & 63, nl = tid >> 6;
    int n = blockIdx.x * 8 + nl;  // 3125*8 == 25000 exactly

    __shared__ float ps[N_GRAPHS * HID];
    for (int i = tid; i < N_GRAPHS * HID; i += 512) ps[i] = 0.f;
    __syncthreads();

    const float inv = 1.0f / (float)N_NODES;
    float mu = g_sums[k] * inv;
    float var = g_sumsq[k] * inv - mu * mu;
    float rstd = rsqrtf(var + 1e-5f);
    float v = gamma[k] * (g_R[n * HID + k] - mu) * rstd + beta[k];
    if (shortcut) v += hin[n * HID + k];
    hout[n * HID + k] = v;

    int g = gids[n];
    atomicAdd(&ps[g * HID + k], v);
    __syncthreads();

    int gmin = gids[blockIdx.x * 8];
    int gmax = gids[blockIdx.x * 8 + 7];        // ids sorted -> contiguous span
    int span = (gmax - gmin + 1) * HID;
    for (int i = tid; i < span; i += 512)
        atomicAdd(&g_pooled[gmin * HID + i], ps[gmin * HID + i]);

    // ---- last-block classifier ----
    __shared__ int s_last;
    __threadfence();
    __syncthreads();
    if (tid == 0) s_last = (atomicAdd(&g_done, 1) == (int)gridDim.x - 1) ? 1 : 0;
    __syncthreads();
    if (!s_last) return;

    __shared__ float xp[N_GRAPHS * HID];   // 1024
    __shared__ float y[N_GRAPHS * 32];     // 512
    __shared__ float mus[32], rss[32];
    for (int i = tid; i < N_GRAPHS * HID; i += 512) xp[i] = g_pooled[i];
    __syncthreads();
    {
        int r = tid >> 5, c = tid & 31;
        float acc = cb1[c];
        #pragma unroll 8
        for (int j = 0; j < HID; j++) acc += xp[r * HID + j] * cW1[j * 32 + c];
        y[r * 32 + c] = acc;
    }
    __syncthreads();
    if (tid < 32) {
        float s = 0.f, s2 = 0.f;
        #pragma unroll
        for (int r = 0; r < N_GRAPHS; r++) {
            float vv = y[r * 32 + tid];
            s += vv; s2 += vv * vv;
        }
        float m = s / (float)N_GRAPHS;
        float vr = s2 / (float)N_GRAPHS - m * m;
        mus[tid] = m;
        rss[tid] = rsqrtf(vr + 1e-5f);
    }
    __syncthreads();
    {
        int r = tid >> 5, c = tid & 31;
        float vv = cg1[c] * (y[r * 32 + c] - mus[c]) * rss[c] + cbt1[c];
        y[r * 32 + c] = fmaxf(vv, 0.f);
    }
    __syncthreads();
    if (tid < N_GRAPHS * N_CLASSES) {
        int r = tid / N_CLASSES, c = tid % N_CLASSES;
        float acc = cb2[c];
        #pragma unroll
        for (int j = 0; j < 32; j++) acc += y[r * 32 + j] * cW2[j * N_CLASSES + c];
        if (accumulate) out[r * N_CLASSES + c] += acc;
        else            out[r * N_CLASSES + c] = acc;
    }
}

// ---------------- launcher -------------------------------------------------
extern "C" void kernel_launch(void* const* d_in, const int* in_sizes, int n_in,
                              void* d_out, int out_size) {
    const float* feature = (const float*)d_in[0];
    const float* spemb   = (const float*)d_in[1];
    const int*   src     = (const int*)d_in[2];
    const int*   dst     = (const int*)d_in[3];
    const int*   gids    = (const int*)d_in[4];
    const float* W[3]  = { (const float*)d_in[5], (const float*)d_in[6], (const float*)d_in[7] };
    const float* gm[3] = { (const float*)d_in[8], (const float*)d_in[10], (const float*)d_in[12] };
    const float* bt[3] = { (const float*)d_in[9], (const float*)d_in[11], (const float*)d_in[13] };
    const float* cW1  = (const float*)d_in[14];
    const float* cb1  = (const float*)d_in[15];
    const float* cg1  = (const float*)d_in[16];
    const float* cbt1 = (const float*)d_in[17];
    const float* cW2  = (const float*)d_in[18];
    const float* cb2  = (const float*)d_in[19];
    float* out = (float*)d_out;

    // CSR by dst + normalized edge directions (shared by all 3 layers)
    k_zero_cc<<<(N_NODES + 255) / 256, 256>>>();
    k_hist_dir<<<(N_EDGES + 255) / 256, 256>>>(src, dst, spemb);
    k_scan<<<1, 1024>>>();
    k_scatter<<<(N_EDGES + 255) / 256, 256>>>(src, dst);

    int hin = 0, hout = 1;
    for (int L = 0; L < 3; L++) {
        k_edge_agg<<<(N_NODES * 32 + 255) / 256, 256>>>(feature, hin);
        k_gemm_relu<<<(N_NODES + BM - 1) / BM, 256>>>(W[L]);
        k_norm_pool<<<N_NODES / 8, 512>>>(feature, hin, hout, gm[L], bt[L], gids,
                                          L > 0 ? 1 : 0,
                                          cW1, cb1, cg1, cbt1, cW2, cb2,
                                          out, L > 0 ? 1 : 0);
        hin = hout;
        hout = (hout == 1) ? 2 : 1;
    }
}

// round 4
// speedup vs baseline: 1.3749x; 1.3749x over previous
#include <cuda_runtime.h>
#include <cuda_bf16.h>
#include <math.h>

#define N_NODES 25000
#define N_EDGES 400000
#define HID 64
#define EMB 8
#define N_GRAPHS 16
#define N_CLASSES 10
#define KDIM 512   /* EMB*HID */

// ---------------- scratch (device globals; no allocation allowed) ----------
__device__ float g_B[(size_t)N_NODES * KDIM];     // 51.2 MB  B[n, i*64+j]
__device__ float g_hA[N_NODES * HID];
__device__ float g_hB[N_NODES * HID];
__device__ float g_R[N_NODES * HID];              // relu(agg)
__device__ float g_D[(size_t)N_EDGES * EMB];      // directions in ORIGINAL edge order
__device__ int2  g_se[N_EDGES];                   // CSR-ordered {src, edge_id}
__device__ int   g_rowptr[N_NODES + 1];
__device__ int   g_cnt[N_NODES];
__device__ int   g_cur[N_NODES];
__device__ float g_sums[HID];
__device__ float g_sumsq[HID];
__device__ float g_pooled[N_GRAPHS * HID];
__device__ int   g_done;

// ---------------- tf32 helpers ---------------------------------------------
__device__ __forceinline__ unsigned tf32cvt(float x) {
    unsigned r;
    asm("cvt.rna.tf32.f32 %0, %1;" : "=r"(r) : "f"(x));
    return r;
}
__device__ __forceinline__ void mma_tf32(float* c,
                                         unsigned a0, unsigned a1, unsigned a2, unsigned a3,
                                         unsigned b0, unsigned b1) {
    asm volatile(
        "mma.sync.aligned.m16n8k8.row.col.f32.tf32.tf32.f32 "
        "{%0,%1,%2,%3}, {%4,%5,%6,%7}, {%8,%9}, {%0,%1,%2,%3};"
        : "+f"(c[0]), "+f"(c[1]), "+f"(c[2]), "+f"(c[3])
        : "r"(a0), "r"(a1), "r"(a2), "r"(a3), "r"(b0), "r"(b1));
}

// ---------------- CSR build ------------------------------------------------
__global__ void k_zero_cc() {
    int i = blockIdx.x * blockDim.x + threadIdx.x;
    if (i < N_NODES) { g_cnt[i] = 0; g_cur[i] = 0; }
}

// histogram of dst + per-edge normalized direction (coalesced write, edge order)
__global__ void k_hist_dir(const int* __restrict__ src, const int* __restrict__ dst,
                           const float* __restrict__ c) {
    int e = blockIdx.x * blockDim.x + threadIdx.x;
    if (e >= N_EDGES) return;
    int s = src[e], t = dst[e];
    atomicAdd(&g_cnt[t], 1);
    float4 s0 = __ldg((const float4*)&c[s * EMB]);
    float4 s1 = __ldg((const float4*)&c[s * EMB + 4]);
    float4 t0 = __ldg((const float4*)&c[t * EMB]);
    float4 t1 = __ldg((const float4*)&c[t * EMB + 4]);
    float4 d0 = make_float4(s0.x - t0.x, s0.y - t0.y, s0.z - t0.z, s0.w - t0.w);
    float4 d1 = make_float4(s1.x - t1.x, s1.y - t1.y, s1.z - t1.z, s1.w - t1.w);
    float nn = d0.x * d0.x + d0.y * d0.y + d0.z * d0.z + d0.w * d0.w
             + d1.x * d1.x + d1.y * d1.y + d1.z * d1.z + d1.w * d1.w;
    float sc = 1.0f / fmaxf(sqrtf(nn), 1e-12f);
    d0.x *= sc; d0.y *= sc; d0.z *= sc; d0.w *= sc;
    d1.x *= sc; d1.y *= sc; d1.z *= sc; d1.w *= sc;
    *(float4*)&g_D[(size_t)e * EMB]     = d0;
    *(float4*)&g_D[(size_t)e * EMB + 4] = d1;
}

// single-block scan: 1024 threads x 25 contiguous counts each (25600 >= 25001)
__global__ void k_scan() {
    const int PER = 25;
    __shared__ int wsum[32];
    int tid = threadIdx.x, lane = tid & 31, wid = tid >> 5;
    int base = tid * PER;
    int v[PER];
    int s = 0;
    #pragma unroll
    for (int j = 0; j < PER; j++) {
        int i = base + j;
        int cv = (i < N_NODES) ? g_cnt[i] : 0;
        v[j] = s;
        s += cv;
    }
    int x = s;
    #pragma unroll
    for (int o = 1; o < 32; o <<= 1) {
        int t = __shfl_up_sync(0xffffffffu, x, o);
        if (lane >= o) x += t;
    }
    if (lane == 31) wsum[wid] = x;
    __syncthreads();
    if (wid == 0) {
        int w = wsum[lane];
        #pragma unroll
        for (int o = 1; o < 32; o <<= 1) {
            int t = __shfl_up_sync(0xffffffffu, w, o);
            if (lane >= o) w += t;
        }
        wsum[lane] = w;
    }
    __syncthreads();
    int off = x - s + (wid > 0 ? wsum[wid - 1] : 0);
    #pragma unroll
    for (int j = 0; j < PER; j++) {
        int i = base + j;
        if (i <= N_NODES) g_rowptr[i] = off + v[j];
    }
}

// scatter edge -> CSR slot; only 8 bytes scattered per edge
__global__ void k_scatter(const int* __restrict__ src, const int* __restrict__ dst) {
    int e = blockIdx.x * blockDim.x + threadIdx.x;
    if (e >= N_EDGES) return;
    int s = src[e], t = dst[e];
    int p = g_rowptr[t] + atomicAdd(&g_cur[t], 1);
    g_se[p] = make_int2(s, e);
}

// ---------------- edge aggregation: B[n,i,j] = sum_{e:dst=n} d_i * h[src,j] ----
__global__ void k_edge_agg(const float* __restrict__ feat, int hsel) {
    if (blockIdx.x == 0) {   // piggyback: zero per-layer reduction buffers
        int t = threadIdx.x;
        if (t < HID) { g_sums[t] = 0.f; g_sumsq[t] = 0.f; }
        if (t == 0) g_done = 0;
        for (int i = t; i < N_GRAPHS * HID; i += blockDim.x) g_pooled[i] = 0.f;
    }
    const float* __restrict__ h = (hsel == 0) ? feat : ((hsel == 1) ? g_hA : g_hB);
    int w = (blockIdx.x * blockDim.x + threadIdx.x) >> 5;
    int lane = threadIdx.x & 31;
    if (w >= N_NODES) return;
    int e0 = g_rowptr[w], e1 = g_rowptr[w + 1];
    float a0[EMB], a1[EMB];
    #pragma unroll
    for (int i = 0; i < EMB; i++) { a0[i] = 0.f; a1[i] = 0.f; }
    #pragma unroll 2
    for (int e = e0; e < e1; e++) {
        int2 se = __ldg(&g_se[e]);
        float4 d0 = __ldg((const float4*)&g_D[(size_t)se.y * EMB]);
        float4 d1 = __ldg((const float4*)&g_D[(size_t)se.y * EMB + 4]);
        float h0 = __ldg(&h[se.x * HID + lane]);
        float h1 = __ldg(&h[se.x * HID + 32 + lane]);
        a0[0] += d0.x * h0;  a1[0] += d0.x * h1;
        a0[1] += d0.y * h0;  a1[1] += d0.y * h1;
        a0[2] += d0.z * h0;  a1[2] += d0.z * h1;
        a0[3] += d0.w * h0;  a1[3] += d0.w * h1;
        a0[4] += d1.x * h0;  a1[4] += d1.x * h1;
        a0[5] += d1.y * h0;  a1[5] += d1.y * h1;
        a0[6] += d1.z * h0;  a1[6] += d1.z * h1;
        a0[7] += d1.w * h0;  a1[7] += d1.w * h1;
    }
    float* out = &g_B[(size_t)w * KDIM];
    #pragma unroll
    for (int i = 0; i < EMB; i++) {
        out[i * HID + lane] = a0[i];
        out[i * HID + 32 + lane] = a1[i];
    }
}

// -------- tf32 tensor-core GEMM: R = relu(B[25000,512] @ W[512,64]) + BN stats --
// 64x64 tile per block, 128 threads (4 warps), warp = 16 rows x 64 cols
// smem holds tf32-converted operands; frag layouts chosen bank-conflict-free.
#define BM 64
#define BK 32
__global__ void k_gemm_relu(const float* __restrict__ W) {
    __shared__ unsigned As[BM][36];   // stride 36: A-frag loads conflict-free
    __shared__ unsigned Bs[BK][72];   // stride 72: B-frag loads conflict-free
    int tid = threadIdx.x;            // 128
    int lane = tid & 31, w = tid >> 5;
    int g = lane >> 2, tig = lane & 3;
    int rowBase = blockIdx.x * BM;
    int wrow = w * 16;
    float acc[8][4];
    #pragma unroll
    for (int nt = 0; nt < 8; nt++)
        #pragma unroll
        for (int j = 0; j < 4; j++) acc[nt][j] = 0.f;

    for (int kb = 0; kb < KDIM; kb += BK) {
        // A tile: 64 rows x 32 k = 512 float4, 4 per thread; cvt to tf32 at store
        #pragma unroll
        for (int it = 0; it < 4; it++) {
            int f = tid + 128 * it;
            int r = f >> 3, q = f & 7;
            int grow = rowBase + r;
            float4 v = make_float4(0.f, 0.f, 0.f, 0.f);
            if (grow < N_NODES)
                v = *(const float4*)&g_B[(size_t)grow * KDIM + kb + q * 4];
            As[r][q * 4]     = tf32cvt(v.x);
            As[r][q * 4 + 1] = tf32cvt(v.y);
            As[r][q * 4 + 2] = tf32cvt(v.z);
            As[r][q * 4 + 3] = tf32cvt(v.w);
        }
        // W tile: 32 x 64 = 512 float4, 4 per thread
        #pragma unroll
        for (int it = 0; it < 4; it++) {
            int f = tid + 128 * it;
            int k = f >> 4, q = f & 15;
            float4 v = *(const float4*)&W[(kb + k) * HID + q * 4];
            Bs[k][q * 4]     = tf32cvt(v.x);
            Bs[k][q * 4 + 1] = tf32cvt(v.y);
            Bs[k][q * 4 + 2] = tf32cvt(v.z);
            Bs[k][q * 4 + 3] = tf32cvt(v.w);
        }
        __syncthreads();
        #pragma unroll
        for (int kk = 0; kk < 4; kk++) {
            unsigned a0 = As[wrow + g][kk * 8 + tig];
            unsigned a1 = As[wrow + g + 8][kk * 8 + tig];
            unsigned a2 = As[wrow + g][kk * 8 + tig + 4];
            unsigned a3 = As[wrow + g + 8][kk * 8 + tig + 4];
            #pragma unroll
            for (int nt = 0; nt < 8; nt++) {
                unsigned b0 = Bs[kk * 8 + tig][nt * 8 + g];
                unsigned b1 = Bs[kk * 8 + tig + 4][nt * 8 + g];
                mma_tf32(acc[nt], a0, a1, a2, a3, b0, b1);
            }
        }
        __syncthreads();
    }

    // epilogue: relu + store + column stats
    // thread owns cols {nt*8+tig*2, +1}, rows {g, g+8} of this warp's 16-row slab
    int r0 = rowBase + wrow + g;
    int r1 = r0 + 8;
    float cS[8][2], cQ[8][2];
    #pragma unroll
    for (int nt = 0; nt < 8; nt++) {
        float v0 = fmaxf(acc[nt][0], 0.f);   // (r0, col)
        float v1 = fmaxf(acc[nt][1], 0.f);   // (r0, col+1)
        float v2 = fmaxf(acc[nt][2], 0.f);   // (r1, col)
        float v3 = fmaxf(acc[nt][3], 0.f);   // (r1, col+1)
        int col = nt * 8 + tig * 2;
        if (r0 < N_NODES) *(float2*)&g_R[r0 * HID + col] = make_float2(v0, v1);
        if (r1 < N_NODES) *(float2*)&g_R[r1 * HID + col] = make_float2(v2, v3);
        cS[nt][0] = v0 + v2;  cQ[nt][0] = v0 * v0 + v2 * v2;
        cS[nt][1] = v1 + v3;  cQ[nt][1] = v1 * v1 + v3 * v3;
    }
    // butterfly-reduce across g (lane bits 2,3,4)
    #pragma unroll
    for (int o = 16; o >= 4; o >>= 1) {
        #pragma unroll
        for (int nt = 0; nt < 8; nt++) {
            cS[nt][0] += __shfl_xor_sync(0xffffffffu, cS[nt][0], o);
            cS[nt][1] += __shfl_xor_sync(0xffffffffu, cS[nt][1], o);
            cQ[nt][0] += __shfl_xor_sync(0xffffffffu, cQ[nt][0], o);
            cQ[nt][1] += __shfl_xor_sync(0xffffffffu, cQ[nt][1], o);
        }
    }
    __syncthreads();
    float* smr = (float*)&As[0][0];   // 4 warps x 64 cols x2 = 512 floats (fits)
    if (g == 0) {
        #pragma unroll
        for (int nt = 0; nt < 8; nt++) {
            int col = nt * 8 + tig * 2;
            smr[w * HID + col]           = cS[nt][0];
            smr[w * HID + col + 1]       = cS[nt][1];
            smr[256 + w * HID + col]     = cQ[nt][0];
            smr[256 + w * HID + col + 1] = cQ[nt][1];
        }
    }
    __syncthreads();
    if (tid < HID) {
        float s = 0.f, s2 = 0.f;
        #pragma unroll
        for (int ww = 0; ww < 4; ww++) {
            s  += smr[ww * HID + tid];
            s2 += smr[256 + ww * HID + tid];
        }
        atomicAdd(&g_sums[tid], s);
        atomicAdd(&g_sumsq[tid], s2);
    }
}

// ------- BN normalize + shortcut + pooling + (last block) classifier -------
__global__ void k_norm_pool(const float* __restrict__ feat, int hinsel, int houtsel,
                            const float* __restrict__ gamma, const float* __restrict__ beta,
                            const int* __restrict__ gids, int shortcut,
                            const float* __restrict__ cW1, const float* __restrict__ cb1,
                            const float* __restrict__ cg1, const float* __restrict__ cbt1,
                            const float* __restrict__ cW2, const float* __restrict__ cb2,
                            float* __restrict__ out, int accumulate) {
    const float* __restrict__ hin = (hinsel == 0) ? feat : ((hinsel == 1) ? g_hA : g_hB);
    float* hout = (houtsel == 1) ? g_hA : g_hB;
    int tid = threadIdx.x;        // 512 -> 8 nodes x 64 cols per block
    int k = tid & 63, nl = tid >> 6;
    int n = blockIdx.x * 8 + nl;  // 3125*8 == 25000 exactly

    __shared__ float ps[N_GRAPHS * HID];
    for (int i = tid; i < N_GRAPHS * HID; i += 512) ps[i] = 0.f;
    __syncthreads();

    const float inv = 1.0f / (float)N_NODES;
    float mu = g_sums[k] * inv;
    float var = g_sumsq[k] * inv - mu * mu;
    float rstd = rsqrtf(var + 1e-5f);
    float v = gamma[k] * (g_R[n * HID + k] - mu) * rstd + beta[k];
    if (shortcut) v += hin[n * HID + k];
    hout[n * HID + k] = v;

    int g = gids[n];
    atomicAdd(&ps[g * HID + k], v);
    __syncthreads();

    int gmin = gids[blockIdx.x * 8];
    int gmax = gids[blockIdx.x * 8 + 7];        // ids sorted -> contiguous span
    int span = (gmax - gmin + 1) * HID;
    for (int i = tid; i < span; i += 512)
        atomicAdd(&g_pooled[gmin * HID + i], ps[gmin * HID + i]);

    // ---- last-block classifier ----
    __shared__ int s_last;
    __threadfence();
    __syncthreads();
    if (tid == 0) s_last = (atomicAdd(&g_done, 1) == (int)gridDim.x - 1) ? 1 : 0;
    __syncthreads();
    if (!s_last) return;

    __shared__ float xp[N_GRAPHS * HID];   // 1024
    __shared__ float y[N_GRAPHS * 32];     // 512
    __shared__ float mus[32], rss[32];
    for (int i = tid; i < N_GRAPHS * HID; i += 512) xp[i] = g_pooled[i];
    __syncthreads();
    {
        int r = tid >> 5, c = tid & 31;
        float acc = cb1[c];
        #pragma unroll 8
        for (int j = 0; j < HID; j++) acc += xp[r * HID + j] * cW1[j * 32 + c];
        y[r * 32 + c] = acc;
    }
    __syncthreads();
    if (tid < 32) {
        float s = 0.f, s2 = 0.f;
        #pragma unroll
        for (int r = 0; r < N_GRAPHS; r++) {
            float vv = y[r * 32 + tid];
            s += vv; s2 += vv * vv;
        }
        float m = s / (float)N_GRAPHS;
        float vr = s2 / (float)N_GRAPHS - m * m;
        mus[tid] = m;
        rss[tid] = rsqrtf(vr + 1e-5f);
    }
    __syncthreads();
    {
        int r = tid >> 5, c = tid & 31;
        float vv = cg1[c] * (y[r * 32 + c] - mus[c]) * rss[c] + cbt1[c];
        y[r * 32 + c] = fmaxf(vv, 0.f);
    }
    __syncthreads();
    if (tid < N_GRAPHS * N_CLASSES) {
        int r = tid / N_CLASSES, c = tid % N_CLASSES;
        float acc = cb2[c];
        #pragma unroll
        for (int j = 0; j < 32; j++) acc += y[r * 32 + j] * cW2[j * N_CLASSES + c];
        if (accumulate) out[r * N_CLASSES + c] += acc;
        else            out[r * N_CLASSES + c] = acc;
    }
}

// ---------------- launcher -------------------------------------------------
extern "C" void kernel_launch(void* const* d_in, const int* in_sizes, int n_in,
                              void* d_out, int out_size) {
    const float* feature = (const float*)d_in[0];
    const float* spemb   = (const float*)d_in[1];
    const int*   src     = (const int*)d_in[2];
    const int*   dst     = (const int*)d_in[3];
    const int*   gids    = (const int*)d_in[4];
    const float* W[3]  = { (const float*)d_in[5], (const float*)d_in[6], (const float*)d_in[7] };
    const float* gm[3] = { (const float*)d_in[8], (const float*)d_in[10], (const float*)d_in[12] };
    const float* bt[3] = { (const float*)d_in[9], (const float*)d_in[11], (const float*)d_in[13] };
    const float* cW1  = (const float*)d_in[14];
    const float* cb1  = (const float*)d_in[15];
    const float* cg1  = (const float*)d_in[16];
    const float* cbt1 = (const float*)d_in[17];
    const float* cW2  = (const float*)d_in[18];
    const float* cb2  = (const float*)d_in[19];
    float* out = (float*)d_out;

    // CSR by dst + normalized edge directions (shared by all 3 layers)
    k_zero_cc<<<(N_NODES + 255) / 256, 256>>>();
    k_hist_dir<<<(N_EDGES + 255) / 256, 256>>>(src, dst, spemb);
    k_scan<<<1, 1024>>>();
    k_scatter<<<(N_EDGES + 255) / 256, 256>>>(src, dst);

    int hin = 0, hout = 1;
    for (int L = 0; L < 3; L++) {
        k_edge_agg<<<(N_NODES * 32 + 255) / 256, 256>>>(feature, hin);
        k_gemm_relu<<<(N_NODES + BM - 1) / BM, 128>>>(W[L]);
        k_norm_pool<<<N_NODES / 8, 512>>>(feature, hin, hout, gm[L], bt[L], gids,
                                          L > 0 ? 1 : 0,
                                          cW1, cb1, cg1, cbt1, cW2, cb2,
                                          out, L > 0 ? 1 : 0);
        hin = hout;
        hout = (hout == 1) ? 2 : 1;
    }
}